// round 1
// baseline (speedup 1.0000x reference)
#include <cuda_runtime.h>
#include <math.h>

// ---------------------------------------------------------------------------
// Mesh rasterizer (pytorch3d-style) reimplementation.
// Outputs (concatenated float32, reference tuple order):
//   [0)                npix*C   pix_feats  (B,H,W,1,C)
//   [npix*C)           npix     pix_to_face (float-cast int)
//   [npix*(C+1))       npix     zbuf
//   [npix*(C+2))       3*npix   bary
//   [npix*(C+5))       npix     dists
// ---------------------------------------------------------------------------

#define VMAX   16384
#define FMAX   32768
#define PIXMAX 65536
#define NSPLIT 8
#define CH     256
#define TILE   16

__device__ float g_vx[VMAX], g_vy[VMAX], g_vz[VMAX];

__device__ float g_fx0[FMAX], g_fy0[FMAX], g_fz0[FMAX];
__device__ float g_fx1[FMAX], g_fy1[FMAX], g_fz1[FMAX];
__device__ float g_fx2[FMAX], g_fy2[FMAX], g_fz2[FMAX];
__device__ float g_finva[FMAX], g_fz01[FMAX], g_fzskip[FMAX];
__device__ float g_bxmin[FMAX], g_bxmax[FMAX], g_bymin[FMAX], g_bymax[FMAX];

__device__ float g_pz[NSPLIT * PIXMAX];
__device__ int   g_pidx[NSPLIT * PIXMAX];
__device__ int   g_widx[PIXMAX];
__device__ float g_wb[PIXMAX * 3];

__device__ __forceinline__ float f_inf() { return __int_as_float(0x7f800000); }

// ------------------------- vertex transform -------------------------------
__global__ void k_vertex(const float* __restrict__ pos,
                         const float* __restrict__ K,
                         const float* __restrict__ RT,
                         int V, float Wf, float Hf)
{
    int v = blockIdx.x * blockDim.x + threadIdx.x;
    if (v >= V) return;
    float x = pos[3 * v + 0], y = pos[3 * v + 1], z = pos[3 * v + 2];

    const float sgn0 = -1.0f, sgn1 = -1.0f, sgn2 = 1.0f;
    float vv[3];
#pragma unroll
    for (int j = 0; j < 3; j++) {
        float sg = (j == 0) ? sgn0 : (j == 1 ? sgn1 : sgn2);
        float Rp0 = __fmul_rn(RT[j * 4 + 0], sg);
        float Rp1 = __fmul_rn(RT[j * 4 + 1], sg);
        float Rp2 = __fmul_rn(RT[j * 4 + 2], sg);
        float Tp  = __fmul_rn(RT[j * 4 + 3], sg);
        float a = __fmul_rn(x, Rp0);
        a = __fadd_rn(a, __fmul_rn(y, Rp1));
        a = __fadd_rn(a, __fmul_rn(z, Rp2));
        vv[j] = __fadd_rn(a, Tp);
    }
    float scale = __fmul_rn(fminf(Hf, Wf), 0.5f);           // exact for ints
    float fx = __fdiv_rn(K[0], scale);
    float fy = __fdiv_rn(K[4], scale);
    float p0x = -__fdiv_rn(__fsub_rn(K[2], __fmul_rn(Wf, 0.5f)), scale);
    float p0y = -__fdiv_rn(__fsub_rn(K[5], __fmul_rn(Hf, 0.5f)), scale);

    float zz = vv[2];
    float xn = __fadd_rn(__fdiv_rn(__fmul_rn(fx, vv[0]), zz), p0x);
    float yn = __fadd_rn(__fdiv_rn(__fmul_rn(fy, vv[1]), zz), p0y);
    g_vx[v] = xn; g_vy[v] = yn; g_vz[v] = zz;
}

// ------------------------- per-face precompute -----------------------------
__global__ void k_face(const int* __restrict__ faces, int Fn)
{
    int f = blockIdx.x * blockDim.x + threadIdx.x;
    if (f >= Fn) return;
    int i0 = faces[3 * f + 0], i1 = faces[3 * f + 1], i2 = faces[3 * f + 2];
    float x0 = g_vx[i0], y0 = g_vy[i0], z0 = g_vz[i0];
    float x1 = g_vx[i1], y1 = g_vy[i1], z1 = g_vz[i1];
    float x2 = g_vx[i2], y2 = g_vy[i2], z2 = g_vz[i2];

    float area = __fsub_rn(__fmul_rn(__fsub_rn(x1, x0), __fsub_rn(y2, y0)),
                           __fmul_rn(__fsub_rn(y1, y0), __fsub_rn(x2, x0)));
    bool ok = (area > 1e-8f) && (z0 > 0.0f) && (z1 > 0.0f) && (z2 > 0.0f);
    float inva = ok ? __fdiv_rn(1.0f, area) : 0.0f;

    g_fx0[f] = x0; g_fy0[f] = y0; g_fz0[f] = z0;
    g_fx1[f] = x1; g_fy1[f] = y1; g_fz1[f] = z1;
    g_fx2[f] = x2; g_fy2[f] = y2; g_fz2[f] = z2;
    g_finva[f] = inva;
    g_fz01[f]  = __fmul_rn(z0, z1);
    float zmn = fminf(z0, fminf(z1, z2));
    g_fzskip[f] = ok ? (zmn - 1e-4f) : f_inf();
    const float M = 5e-3f;                 // conservative bbox margin
    g_bxmin[f] = fminf(x0, fminf(x1, x2)) - M;
    g_bxmax[f] = fmaxf(x0, fmaxf(x1, x2)) + M;
    g_bymin[f] = fminf(y0, fminf(y1, y2)) - M;
    g_bymax[f] = fmaxf(y0, fmaxf(y1, y2)) + M;
}

// exact perspective-correct bary + zpix, replicating reference op order
__device__ __forceinline__ void eval_exact(
    float px, float py,
    float x0, float y0, float z0, float x1, float y1, float z1,
    float x2, float y2, float z2, float inva, float z01,
    bool& inside, float& zpix, float& d0, float& d1, float& d2)
{
    float dx0 = __fsub_rn(x0, px), dy0 = __fsub_rn(y0, py);
    float dx1 = __fsub_rn(x1, px), dy1 = __fsub_rn(y1, py);
    float dx2 = __fsub_rn(x2, px), dy2 = __fsub_rn(y2, py);
    float w0 = __fmul_rn(__fsub_rn(__fmul_rn(dx1, dy2), __fmul_rn(dy1, dx2)), inva);
    float w1 = __fmul_rn(__fsub_rn(__fmul_rn(dx2, dy0), __fmul_rn(dy2, dx0)), inva);
    float w2 = __fmul_rn(__fsub_rn(__fmul_rn(dx0, dy1), __fmul_rn(dy0, dx1)), inva);
    inside = (w0 >= 0.0f) && (w1 >= 0.0f) && (w2 >= 0.0f);
    if (!inside) { zpix = f_inf(); d0 = d1 = d2 = 0.0f; return; }
    float l0 = __fmul_rn(__fmul_rn(w0, z1), z2);
    float l1 = __fmul_rn(__fmul_rn(z0, w1), z2);
    float l2 = __fmul_rn(z01, w2);
    float s  = __fadd_rn(__fadd_rn(l0, l1), l2);
    float sden = (s == 0.0f) ? 1.0f : s;
    float b0 = __fdiv_rn(l0, sden);
    float b1 = __fdiv_rn(l1, sden);
    float b2 = __fdiv_rn(l2, sden);
    b0 = fmaxf(b0, 0.0f); b1 = fmaxf(b1, 0.0f); b2 = fmaxf(b2, 0.0f);
    float sb = __fadd_rn(__fadd_rn(b0, b1), b2);
    float den2 = fmaxf(sb, 1e-8f);
    d0 = __fdiv_rn(b0, den2);
    d1 = __fdiv_rn(b1, den2);
    d2 = __fdiv_rn(b2, den2);
    zpix = __fadd_rn(__fadd_rn(__fmul_rn(d0, z0), __fmul_rn(d1, z1)),
                     __fmul_rn(d2, z2));
}

// ------------------------- rasterize (tiled) -------------------------------
__global__ void __launch_bounds__(256) k_raster(int W, int H, int Fn, int npix)
{
    __shared__ float s[16][CH];
    int tilesX = (W + TILE - 1) / TILE;
    int tile = blockIdx.x;
    int tx = tile % tilesX, ty = tile / tilesX;
    int lx = threadIdx.x & (TILE - 1), ly = threadIdx.x / TILE;
    int j = tx * TILE + lx, i = ty * TILE + ly;
    bool live = (j < W) && (i < H);

    float px = 0.0f, py = 0.0f;
    if (live) {
        px = __fsub_rn(1.0f, __fdiv_rn(__fadd_rn(__fmul_rn(2.0f, (float)j), 1.0f), (float)W));
        py = __fsub_rn(1.0f, __fdiv_rn(__fadd_rn(__fmul_rn(2.0f, (float)i), 1.0f), (float)H));
    }

    int split = blockIdx.y;
    int per = (Fn + NSPLIT - 1) / NSPLIT;
    int f0 = split * per;
    int f1 = min(Fn, f0 + per);

    float bestZ = f_inf();
    int   bestI = -1;

    for (int base = f0; base < f1; base += CH) {
        int n = min(CH, f1 - base);
        __syncthreads();
        if ((int)threadIdx.x < n) {
            int t = threadIdx.x, g = base + t;
            s[0][t] = g_fx0[g];  s[1][t] = g_fy0[g];  s[2][t] = g_fz0[g];
            s[3][t] = g_fx1[g];  s[4][t] = g_fy1[g];  s[5][t] = g_fz1[g];
            s[6][t] = g_fx2[g];  s[7][t] = g_fy2[g];  s[8][t] = g_fz2[g];
            s[9][t] = g_finva[g]; s[10][t] = g_fz01[g]; s[11][t] = g_fzskip[g];
            s[12][t] = g_bxmin[g]; s[13][t] = g_bxmax[g];
            s[14][t] = g_bymin[g]; s[15][t] = g_bymax[g];
        }
        __syncthreads();
        if (!live) continue;
        for (int k = 0; k < n; k++) {
            float zskip = s[11][k];
            if (zskip >= bestZ) continue;                 // conservative z cull
            if (px < s[12][k] || px > s[13][k] ||
                py < s[14][k] || py > s[15][k]) continue; // conservative bbox
            bool inside; float zpix, d0, d1, d2;
            eval_exact(px, py,
                       s[0][k], s[1][k], s[2][k],
                       s[3][k], s[4][k], s[5][k],
                       s[6][k], s[7][k], s[8][k],
                       s[9][k], s[10][k],
                       inside, zpix, d0, d1, d2);
            if (inside && zpix < bestZ) { bestZ = zpix; bestI = base + k; }
        }
    }
    if (live) {
        int pix = i * W + j;
        g_pz[split * npix + pix]   = bestZ;
        g_pidx[split * npix + pix] = bestI;
    }
}

// ------------------------- merge + scalar outputs --------------------------
__global__ void k_merge(float* __restrict__ out, int W, int H, int npix, int C)
{
    int pix = blockIdx.x * blockDim.x + threadIdx.x;
    if (pix >= npix) return;
    float bz = f_inf(); int bi = -1;
#pragma unroll
    for (int sp = 0; sp < NSPLIT; sp++) {
        float z = g_pz[sp * npix + pix];
        int   id = g_pidx[sp * npix + pix];
        if (id >= 0 && z < bz) { bz = z; bi = id; }   // ascending idx ranges -> argmin-first
    }

    float p2f, zb, ba0, ba1, ba2, ds;
    if (bi < 0) {
        p2f = -1.0f; zb = -1.0f; ba0 = ba1 = ba2 = -1.0f; ds = -1.0f;
    } else {
        int i = pix / W, j = pix % W;
        float px = __fsub_rn(1.0f, __fdiv_rn(__fadd_rn(__fmul_rn(2.0f, (float)j), 1.0f), (float)W));
        float py = __fsub_rn(1.0f, __fdiv_rn(__fadd_rn(__fmul_rn(2.0f, (float)i), 1.0f), (float)H));
        bool inside; float zpix, d0, d1, d2;
        eval_exact(px, py,
                   g_fx0[bi], g_fy0[bi], g_fz0[bi],
                   g_fx1[bi], g_fy1[bi], g_fz1[bi],
                   g_fx2[bi], g_fy2[bi], g_fz2[bi],
                   g_finva[bi], g_fz01[bi],
                   inside, zpix, d0, d1, d2);
        p2f = (float)bi; zb = bz; ba0 = d0; ba1 = d1; ba2 = d2; ds = 0.0f;
        g_wb[3 * pix + 0] = d0; g_wb[3 * pix + 1] = d1; g_wb[3 * pix + 2] = d2;
    }
    g_widx[pix] = bi;

    size_t o1 = (size_t)npix * (size_t)C;
    out[o1 + pix] = p2f;
    out[o1 + npix + pix] = zb;
    out[o1 + 2 * (size_t)npix + 3 * (size_t)pix + 0] = ba0;
    out[o1 + 2 * (size_t)npix + 3 * (size_t)pix + 1] = ba1;
    out[o1 + 2 * (size_t)npix + 3 * (size_t)pix + 2] = ba2;
    out[o1 + 5 * (size_t)npix + pix] = ds;
}

// ------------------------- feature interpolation ---------------------------
__global__ void k_feats(float* __restrict__ out,
                        const float* __restrict__ feats,
                        const int* __restrict__ faces,
                        int npix, int C)
{
    int gw = (blockIdx.x * blockDim.x + threadIdx.x) >> 5;
    int lane = threadIdx.x & 31;
    if (gw >= npix) return;
    float* o = out + (size_t)gw * (size_t)C;
    int bi = g_widx[gw];
    if (bi < 0) {
        for (int c = lane; c < C; c += 32) o[c] = 0.0f;
        return;
    }
    int v0 = faces[3 * bi + 0], v1 = faces[3 * bi + 1], v2 = faces[3 * bi + 2];
    float b0 = g_wb[3 * gw + 0], b1 = g_wb[3 * gw + 1], b2 = g_wb[3 * gw + 2];
    const float* f0 = feats + (size_t)v0 * (size_t)C;
    const float* f1 = feats + (size_t)v1 * (size_t)C;
    const float* f2 = feats + (size_t)v2 * (size_t)C;
    for (int c = lane; c < C; c += 32) {
        float val = __fadd_rn(__fadd_rn(__fmul_rn(b0, f0[c]),
                                        __fmul_rn(b1, f1[c])),
                              __fmul_rn(b2, f2[c]));
        o[c] = val;
    }
}

// ------------------------- launch -----------------------------------------
extern "C" void kernel_launch(void* const* d_in, const int* in_sizes, int n_in,
                              void* d_out, int out_size)
{
    const float* positions = (const float*)d_in[0];
    const float* features  = (const float*)d_in[1];
    const int*   faces     = (const int*)d_in[2];
    const float* K         = (const float*)d_in[3];
    const float* RT        = (const float*)d_in[4];

    int V  = in_sizes[0] / 3;
    int C  = in_sizes[1] / V;
    int Fn = in_sizes[2] / 3;
    int npix = out_size / (C + 6);
    int W = (int)(sqrt((double)npix) + 0.5);
    if (W <= 0) W = 1;
    int H = npix / W;
    float* out = (float*)d_out;

    k_vertex<<<(V + 255) / 256, 256>>>(positions, K, RT, V, (float)W, (float)H);
    k_face<<<(Fn + 255) / 256, 256>>>(faces, Fn);

    int tilesX = (W + TILE - 1) / TILE;
    int tilesY = (H + TILE - 1) / TILE;
    dim3 rg(tilesX * tilesY, NSPLIT);
    k_raster<<<rg, 256>>>(W, H, Fn, npix);

    k_merge<<<(npix + 255) / 256, 256>>>(out, W, H, npix, C);
    k_feats<<<(npix + 7) / 8, 256>>>(out, features, faces, npix, C);
}